// round 2
// baseline (speedup 1.0000x reference)
#include <cuda_runtime.h>
#include <math.h>
#include <stdint.h>

// Problem constants
#define BATCH   8
#define SEQ     2048
#define HID     1024
#define NPB     (SEQ * HID)        // 2,097,152 elements per batch
#define VEC_PB  (NPB / 4)          // 524,288 float4 per batch
#define TOTALV  (BATCH * VEC_PB)   // 4,194,304 float4 total
#define RANK0   1048576u           // index (N - k) in ascending sort, k = N/2

// Scratch (static __device__ globals only — no runtime allocation)
__device__ __align__(16) float    g_imp5[5 * HID];       // sigmoid(band)*sigmoid(dim)
__device__ unsigned               g_hist[3][BATCH][2048];
__device__ unsigned               g_prefix[BATCH];
__device__ unsigned               g_rank[BATCH];
__device__ float                  g_thr[BATCH];

__device__ __forceinline__ float sigmoidf_fast(float x) {
    return 1.0f / (1.0f + __expf(-x));
}

// band(t): 0 for t<128, else floor(log2(t>>7)) + 1   (matches _band_index for T=2048, L=4)
__device__ __forceinline__ int band_of(int t) {
    return (t >= 128) ? (32 - __clz(t >> 7)) : 0;
}

// ---------------------------------------------------------------------------
// setup: zero histograms, reset per-batch select state, build importance table
// (runs every replay; must be idempotent)
// ---------------------------------------------------------------------------
__global__ void setup_kernel(const float* __restrict__ bi, const float* __restrict__ di) {
    int i = blockIdx.x * blockDim.x + threadIdx.x;
    if (i < 3 * BATCH * 2048) ((unsigned*)g_hist)[i] = 0;
    if (i < BATCH) { g_prefix[i] = 0u; g_rank[i] = RANK0; }
    if (i < 5 * HID) {
        float sb = sigmoidf_fast(bi[i]);
        float sd = sigmoidf_fast(di[i & (HID - 1)]);
        g_imp5[i] = sb * sd;
    }
}

// compute 4 consecutive importance-weighted |coeffs| for vec index within a batch
__device__ __forceinline__ float4 compute_ci4(const float4* __restrict__ cb, int ve_in_batch) {
    int eb = ve_in_batch << 2;
    int t = eb >> 10;
    int d = eb & (HID - 1);
    int band = band_of(t);
    float4 imp = *reinterpret_cast<const float4*>(&g_imp5[band * HID + d]);
    float4 c = __ldg(&cb[ve_in_batch]);
    float4 r;
    r.x = imp.x * fabsf(c.x);
    r.y = imp.y * fabsf(c.y);
    r.z = imp.z * fabsf(c.z);
    r.w = imp.w * fabsf(c.w);
    return r;
}

// ---------------------------------------------------------------------------
// histogram pass (templated): PASS 0: bits[31:21]; PASS 1: bits[20:10] among
// prefix-matching; PASS 2: bits[9:0] among prefix-matching.
// grid = (64, BATCH), 256 threads. 4-way replicated shared histograms.
// ---------------------------------------------------------------------------
template <int PASS>
__global__ void __launch_bounds__(256) hist_kernel(const float4* __restrict__ coeffs) {
    constexpr int NREP = 4;
    __shared__ unsigned sh[NREP][2048];
    const int tid  = threadIdx.x;
    const int warp = tid >> 5;

    for (int i = tid; i < NREP * 2048; i += 256) ((unsigned*)sh)[i] = 0;
    __syncthreads();

    const int batch = blockIdx.y;
    const unsigned prefix = g_prefix[batch];
    unsigned* h = sh[warp & (NREP - 1)];

    constexpr int PER_BLOCK = VEC_PB / 64;   // 8192 float4 per block
    const int base = blockIdx.x * PER_BLOCK;
    const float4* cb = coeffs + (size_t)batch * VEC_PB;

    constexpr int DIG_SHIFT = (PASS == 0) ? 21 : (PASS == 1) ? 10 : 0;
    constexpr unsigned DIG_MASK = (PASS == 2) ? 1023u : 2047u;
    constexpr int CMP_SHIFT = (PASS == 1) ? 21 : 10;   // unused for PASS==0

    // 2x unrolled: two independent float4 loads in flight per iteration
    for (int i = tid; i < PER_BLOCK; i += 512) {
        float4 ci0 = compute_ci4(cb, base + i);
        float4 ci1 = compute_ci4(cb, base + i + 256);
        unsigned bb[8];
        bb[0] = __float_as_uint(ci0.x); bb[1] = __float_as_uint(ci0.y);
        bb[2] = __float_as_uint(ci0.z); bb[3] = __float_as_uint(ci0.w);
        bb[4] = __float_as_uint(ci1.x); bb[5] = __float_as_uint(ci1.y);
        bb[6] = __float_as_uint(ci1.z); bb[7] = __float_as_uint(ci1.w);
        #pragma unroll
        for (int j = 0; j < 8; j++) {
            bool ok = (PASS == 0) || ((bb[j] >> CMP_SHIFT) == (prefix >> CMP_SHIFT));
            if (ok) atomicAdd(&h[(bb[j] >> DIG_SHIFT) & DIG_MASK], 1u);
        }
    }
    __syncthreads();

    for (int i = tid; i < 2048; i += 256) {
        unsigned s = sh[0][i] + sh[1][i] + sh[2][i] + sh[3][i];
        if (s) atomicAdd(&g_hist[PASS][batch][i], s);
    }
}

// ---------------------------------------------------------------------------
// digit select: one warp per batch. Find digit where cumulative count passes
// the remaining rank; update prefix/rank; after last pass emit threshold.
// ---------------------------------------------------------------------------
template <int PASS>
__global__ void select_kernel() {
    const int b = blockIdx.x;
    const int lane = threadIdx.x;
    const unsigned* __restrict__ h = g_hist[PASS][b];
    constexpr int NB = (PASS == 2) ? 1024 : 2048;
    constexpr int PER = NB / 32;

    unsigned s = 0;
    #pragma unroll
    for (int j = 0; j < PER; j++) s += h[lane * PER + j];

    // inclusive shfl scan -> exclusive
    unsigned v = s;
    #pragma unroll
    for (int o = 1; o < 32; o <<= 1) {
        unsigned t = __shfl_up_sync(0xFFFFFFFFu, v, o);
        if (lane >= o) v += t;
    }
    unsigned excl = v - s;

    const unsigned rank = g_rank[b];
    bool in = (rank >= excl) && (rank < excl + s);
    unsigned m = __ballot_sync(0xFFFFFFFFu, in);
    int L = __ffs(m) - 1;

    if (lane == L) {
        unsigned cum = excl;
        #pragma unroll 1
        for (int j = 0; j < PER; j++) {
            unsigned c = h[lane * PER + j];
            if (rank < cum + c) {
                unsigned dig = (unsigned)(lane * PER + j);
                g_rank[b] = rank - cum;
                constexpr int SHIFT = (PASS == 0) ? 21 : (PASS == 1) ? 10 : 0;
                unsigned p = g_prefix[b] | (dig << SHIFT);
                g_prefix[b] = p;
                if (PASS == 2) g_thr[b] = __uint_as_float(p);
                break;
            }
            cum += c;
        }
    }
}

// ---------------------------------------------------------------------------
// final: out[0..V) = coeffs * mask, out[V..2V) = mask, out[2V..3V) = importance
// ---------------------------------------------------------------------------
__global__ void __launch_bounds__(256) final_kernel(const float4* __restrict__ coeffs,
                                                    const float* __restrict__ temp,
                                                    float4* __restrict__ out) {
    int ve = blockIdx.x * blockDim.x + threadIdx.x;     // 0 .. TOTALV-1
    int batch = ve >> 19;                               // VEC_PB = 2^19
    int vein = ve & (VEC_PB - 1);
    int eb = vein << 2;
    int t = eb >> 10;
    int d = eb & (HID - 1);
    int band = band_of(t);

    float4 imp = *reinterpret_cast<const float4*>(&g_imp5[band * HID + d]);
    float4 c = __ldg(&coeffs[ve]);
    float thr = g_thr[batch];
    float inv_t = __frcp_rn(fabsf(__ldg(&temp[0])));

    float4 mk, fl;
    { float ci = imp.x * fabsf(c.x); mk.x = sigmoidf_fast((ci - thr) * inv_t); fl.x = c.x * mk.x; }
    { float ci = imp.y * fabsf(c.y); mk.y = sigmoidf_fast((ci - thr) * inv_t); fl.y = c.y * mk.y; }
    { float ci = imp.z * fabsf(c.z); mk.z = sigmoidf_fast((ci - thr) * inv_t); fl.z = c.z * mk.z; }
    { float ci = imp.w * fabsf(c.w); mk.w = sigmoidf_fast((ci - thr) * inv_t); fl.w = c.w * mk.w; }

    out[ve] = fl;
    out[TOTALV + ve] = mk;
    out[2 * TOTALV + ve] = imp;
}

// ---------------------------------------------------------------------------
// launch
// ---------------------------------------------------------------------------
extern "C" void kernel_launch(void* const* d_in, const int* in_sizes, int n_in,
                              void* d_out, int out_size) {
    const float* coeffs = (const float*)d_in[0];
    const float* bi     = (const float*)d_in[1];
    const float* di     = (const float*)d_in[2];
    const float* temp   = (const float*)d_in[3];
    float* out = (float*)d_out;

    setup_kernel<<<(3 * BATCH * 2048 + 255) / 256, 256>>>(bi, di);

    dim3 hg(64, BATCH);
    hist_kernel<0><<<hg, 256>>>((const float4*)coeffs);
    select_kernel<0><<<BATCH, 32>>>();
    hist_kernel<1><<<hg, 256>>>((const float4*)coeffs);
    select_kernel<1><<<BATCH, 32>>>();
    hist_kernel<2><<<hg, 256>>>((const float4*)coeffs);
    select_kernel<2><<<BATCH, 32>>>();

    final_kernel<<<TOTALV / 256, 256>>>((const float4*)coeffs, temp, (float4*)out);
}